// round 15
// baseline (speedup 1.0000x reference)
#include <cuda_runtime.h>
#include <cuda_fp16.h>
#include <math.h>

#define NN 4096
#define DIN 256
#define DOUT 256
#define KH 3
#define CAP 384
#define ALAR_BLOCKS 96
#define GEMM_BLOCKS 768
#define TOTAL_BLOCKS (ALAR_BLOCKS + GEMM_BLOCKS)
#define AP 20                 // smem half-row pitch (pad vs bank conflicts)
#define ATHR 512

// scratch (device globals: no allocation allowed)
__device__ __half g_wxh[KH * NN * DOUT];         // 6 MB fp16 (for gather)
__device__ float  g_al[KH * NN * 4];
__device__ float  g_ar[KH * NN * 4];

__device__ __forceinline__ void mma_16816(float c[4], unsigned a0, unsigned a1,
                                          unsigned a2, unsigned a3,
                                          unsigned b0, unsigned b1) {
    asm volatile(
        "mma.sync.aligned.m16n8k16.row.col.f32.f16.f16.f32 "
        "{%0,%1,%2,%3}, {%4,%5,%6,%7}, {%8,%9}, {%0,%1,%2,%3};"
        : "+f"(c[0]), "+f"(c[1]), "+f"(c[2]), "+f"(c[3])
        : "r"(a0), "r"(a1), "r"(a2), "r"(a3), "r"(b0), "r"(b1));
}

// pack 4 0/1 ints into 4 bytes of one u32
__device__ __forceinline__ unsigned pk01(int4 v) {
    return (unsigned)v.x | ((unsigned)v.y << 8) |
           ((unsigned)v.z << 16) | ((unsigned)v.w << 24);
}

// ---------------------------------------------------------------------------
// Kernel A: [al/ar via combined weights] + [HMMA GEMM -> fp16 wxh]
// (mask scan removed — attn reads masks directly now)
// ---------------------------------------------------------------------------
__global__ void __launch_bounds__(256)
fused_gemm_alar(const float* __restrict__ x,
                const float* __restrict__ Wt,
                const float* __restrict__ Wl,
                const float* __restrict__ Wr) {
    __shared__ __align__(16) char smem_raw[8192];

    int bid = blockIdx.x;               // 0 .. 863
    int tx  = threadIdx.x;

    if (bid < ALAR_BLOCKS) {
        // ---------------- alar path: al/ar = x @ (Wt @ W{l,r}.T), fp32 -----
        float* sWc = (float*)smem_raw;  // [256][8]
        int k = bid / 32;
        int chunk = bid % 32;
        int wid = tx >> 5;
        int lane = tx & 31;

        const float* Wtk = Wt + (size_t)k * DIN * DOUT;
        const float* wrow = (wid < 4) ? (Wl + (size_t)(k * 4 + wid) * DOUT)
                                      : (Wr + (size_t)(k * 4 + (wid - 4)) * DOUT);
        float4 wa = *(const float4*)(wrow + lane * 4);
        float4 wb = *(const float4*)(wrow + 128 + lane * 4);

        for (int c = 0; c < 256; c++) {
            float4 ta = *(const float4*)(Wtk + (size_t)c * DOUT + lane * 4);
            float4 tb = *(const float4*)(Wtk + (size_t)c * DOUT + 128 + lane * 4);
            float acc = ta.x * wa.x + ta.y * wa.y + ta.z * wa.z + ta.w * wa.w +
                        tb.x * wb.x + tb.y * wb.y + tb.z * wb.z + tb.w * wb.w;
#pragma unroll
            for (int o = 16; o; o >>= 1)
                acc += __shfl_xor_sync(0xffffffffu, acc, o);
            if (lane == 0) sWc[c * 8 + wid] = acc;
        }
        __syncthreads();

        int rl = tx >> 3;
        int j = tx & 7;
#pragma unroll
        for (int it = 0; it < 4; it++) {
            int row = chunk * 128 + it * 32 + rl;
            const float* xr = x + (size_t)row * DIN;
            float acc = 0.f;
#pragma unroll 8
            for (int c4 = 0; c4 < 64; c4++) {
                float4 xv = *(const float4*)(xr + c4 * 4);
                acc += xv.x * sWc[(c4 * 4 + 0) * 8 + j] +
                       xv.y * sWc[(c4 * 4 + 1) * 8 + j] +
                       xv.z * sWc[(c4 * 4 + 2) * 8 + j] +
                       xv.w * sWc[(c4 * 4 + 3) * 8 + j];
            }
            if (j < 4)
                g_al[((size_t)k * NN + row) * 4 + j] = acc;
            else
                g_ar[((size_t)k * NN + row) * 4 + (j - 4)] = acc;
        }
        return;
    }

    // ---------------- GEMM path (single fp16 HMMA) -------------------------
    {
        __half* sA  = (__half*)smem_raw;                  // 64*AP
        __half* sBt = sA + 64 * AP;

        int gid = bid - ALAR_BLOCKS;    // 0..767
        int k = gid >> 8;
        int rem = gid & 255;
        int row0 = (rem >> 2) * 64;
        int col0 = (rem & 3) * 64;
        const float* B = Wt + (size_t)k * DIN * DOUT;

        int wid = tx >> 5;
        int lane = tx & 31;
        int g = lane >> 2;
        int tg = lane & 3;
        int moff = (wid >> 1) * 16;
        int noff = (wid & 1) * 32;

        float c[4][4];
#pragma unroll
        for (int i = 0; i < 4; i++)
#pragma unroll
            for (int j = 0; j < 4; j++) c[i][j] = 0.f;

        int lm = tx >> 2;
        int lk4 = (tx & 3) * 4;
        int lkr = tx >> 4;
        int ln4 = (tx & 15) * 4;

        for (int ks = 0; ks < 16; ks++) {
            int kk = ks * 16;
            {
                float4 v = *(const float4*)(x + (size_t)(row0 + lm) * DIN + kk + lk4);
                *(__half2*)&sA[lm * AP + lk4]     = __floats2half2_rn(v.x, v.y);
                *(__half2*)&sA[lm * AP + lk4 + 2] = __floats2half2_rn(v.z, v.w);
            }
            {
                float4 w = *(const float4*)(B + (size_t)(kk + lkr) * DOUT + col0 + ln4);
                sBt[(ln4 + 0) * AP + lkr] = __float2half_rn(w.x);
                sBt[(ln4 + 1) * AP + lkr] = __float2half_rn(w.y);
                sBt[(ln4 + 2) * AP + lkr] = __float2half_rn(w.z);
                sBt[(ln4 + 3) * AP + lkr] = __float2half_rn(w.w);
            }
            __syncthreads();

            unsigned a0 = *(unsigned*)&sA[(moff + g) * AP + tg * 2];
            unsigned a1 = *(unsigned*)&sA[(moff + g + 8) * AP + tg * 2];
            unsigned a2 = *(unsigned*)&sA[(moff + g) * AP + tg * 2 + 8];
            unsigned a3 = *(unsigned*)&sA[(moff + g + 8) * AP + tg * 2 + 8];
#pragma unroll
            for (int nb = 0; nb < 4; nb++) {
                unsigned b0 = *(unsigned*)&sBt[(noff + nb * 8 + g) * AP + tg * 2];
                unsigned b1 = *(unsigned*)&sBt[(noff + nb * 8 + g) * AP + tg * 2 + 8];
                mma_16816(c[nb], a0, a1, a2, a3, b0, b1);
            }
            __syncthreads();
        }

        size_t kplane = (size_t)k * NN * DOUT;
#pragma unroll
        for (int nb = 0; nb < 4; nb++) {
            int gcol = col0 + noff + nb * 8 + tg * 2;
            size_t o0 = kplane + (size_t)(row0 + moff + g) * DOUT + gcol;
            size_t o1 = kplane + (size_t)(row0 + moff + g + 8) * DOUT + gcol;
            *(__half2*)(g_wxh + o0) = __floats2half2_rn(c[nb][0], c[nb][1]);
            *(__half2*)(g_wxh + o1) = __floats2half2_rn(c[nb][2], c[nb][3]);
        }
    }
}

// ---------------------------------------------------------------------------
// Kernel C: per-row attention, 512 threads. Reads the 6 mask rows DIRECTLY
// (streaming, evict-first), packs codes in registers, then: compact ->
// single-shot score+exp+sum -> pair write -> 16-warp gather.
// ---------------------------------------------------------------------------
__global__ void __launch_bounds__(ATHR)
attn_kernel(const int* __restrict__ supports,
            const int* __restrict__ atten,
            float* __restrict__ out) {
    int n = blockIdx.x;
    int tid = threadIdx.x;
    int lane = tid & 31;
    int wid = tid >> 5;                 // 0..15

    __shared__ unsigned s_list[CAP];
    __shared__ float s_p[3][CAP];
    __shared__ unsigned long long s_pair[3 * CAP];
    __shared__ float s_acc[16][256];
    __shared__ float s_al[3][4];
    __shared__ float s_red[3][16];
    __shared__ float s_inv[3];
    __shared__ int s_warp[16];
    __shared__ int s_tot;
    __shared__ int s_cnt;

    if (tid < 12) {
        int k = tid >> 2, j = tid & 3;
        s_al[k][j] = g_al[((size_t)k * NN + n) * 4 + j];
    }

    // ---- phase 0: read 6 mask rows directly; pack codes for my 8 positions
    const int4* pa0 = (const int4*)(atten + ((size_t)0 * NN + n) * NN);
    const int4* pa1 = (const int4*)(atten + ((size_t)1 * NN + n) * NN);
    const int4* pa2 = (const int4*)(atten + ((size_t)2 * NN + n) * NN);
    const int4* ps0 = (const int4*)(supports + ((size_t)0 * NN + n) * NN);
    const int4* ps1 = (const int4*)(supports + ((size_t)1 * NN + n) * NN);
    const int4* ps2 = (const int4*)(supports + ((size_t)2 * NN + n) * NN);

    int i0 = tid * 2;                   // int4 index; my elems = tid*8..+7
    int4 A0 = __ldcs(pa0 + i0), B0 = __ldcs(pa0 + i0 + 1);
    int4 A1 = __ldcs(pa1 + i0), B1 = __ldcs(pa1 + i0 + 1);
    int4 A2 = __ldcs(pa2 + i0), B2 = __ldcs(pa2 + i0 + 1);
    int4 Q0 = __ldcs(ps0 + i0), T0 = __ldcs(ps0 + i0 + 1);
    int4 Q1 = __ldcs(ps1 + i0), T1 = __ldcs(ps1 + i0 + 1);
    int4 Q2 = __ldcs(ps2 + i0), T2 = __ldcs(ps2 + i0 + 1);

    unsigned w2[2];
    w2[0] = pk01(A0) | (pk01(A1) << 1) | (pk01(A2) << 2) |
            (pk01(Q0) << 3) | (pk01(Q1) << 4) | (pk01(Q2) << 5);
    w2[1] = pk01(B0) | (pk01(B1) << 1) | (pk01(B2) << 2) |
            (pk01(T0) << 3) | (pk01(T1) << 4) | (pk01(T2) << 5);

    int cnt_local = 0;
#pragma unroll
    for (int q = 0; q < 2; q++)
        cnt_local += __popc(__vcmpne4(w2[q], 0u)) >> 3;

    {
        int incl = cnt_local;
#pragma unroll
        for (int o = 1; o < 32; o <<= 1) {
            int t = __shfl_up_sync(0xffffffffu, incl, o);
            if (lane >= o) incl += t;
        }
        if (lane == 31) s_warp[wid] = incl;
        __syncthreads();
        if (tid < 16) {
            int t = s_warp[tid];
            int p = t;
#pragma unroll
            for (int o = 1; o < 16; o <<= 1) {
                int u = __shfl_up_sync(0xffffu, p, o);
                if (tid >= o) p += u;
            }
            s_warp[tid] = p - t;
            if (tid == 15) s_cnt = p;
        }
        __syncthreads();
        int off = s_warp[wid] + incl - cnt_local;
#pragma unroll
        for (int q = 0; q < 2; q++) {
#pragma unroll
            for (int j = 0; j < 4; j++) {
                unsigned c = (w2[q] >> (8 * j)) & 255u;
                if (c) {
                    unsigned m = (unsigned)(tid * 8 + q * 4 + j);
                    if (off < CAP) s_list[off] = (m << 6) | c;
                    off++;
                }
            }
        }
    }
    __syncthreads();
    int cnt = min(s_cnt, CAP);

    // ---- phase 1: scores + exp + sum + counts, single shot (cnt < 512)
    float sm[3] = {0.f, 0.f, 0.f};
    int ck[3] = {0, 0, 0};
    if (tid < cnt) {
        unsigned v = s_list[tid];
        int m = (int)(v >> 6);
        int code = (int)(v & 63u);
#pragma unroll
        for (int k = 0; k < 3; k++) {
            float4 arv = *(const float4*)(g_ar + ((size_t)k * NN + m) * 4);
            float s = 0.f;
            if (code & 1) s += s_al[k][0] + arv.x;
            if (code & 2) s += s_al[k][1] + arv.y;
            if (code & 4) s += s_al[k][2] + arv.z;
            if (code & (8 << k)) s += s_al[k][3] + arv.w;
            float p = (s != 0.f) ? __expf(s) : 0.f;
            s_p[k][tid] = p;
            sm[k] = p;
            ck[k] = (p != 0.f);
        }
    }
#pragma unroll
    for (int k = 0; k < 3; k++)
#pragma unroll
        for (int o = 16; o; o >>= 1)
            sm[k] += __shfl_xor_sync(0xffffffffu, sm[k], o);
    if (lane == 0) {
#pragma unroll
        for (int k = 0; k < 3; k++) s_red[k][wid] = sm[k];
    }

    int packed = ck[0] | (ck[1] << 10) | (ck[2] << 20);
    int incl = packed;
#pragma unroll
    for (int o = 1; o < 32; o <<= 1) {
        int t = __shfl_up_sync(0xffffffffu, incl, o);
        if (lane >= o) incl += t;
    }
    if (lane == 31) s_warp[wid] = incl;
    __syncthreads();
    if (tid == 0) {
#pragma unroll
        for (int k = 0; k < 3; k++) {
            float t = 0.f;
#pragma unroll
            for (int w = 0; w < 16; w++) t += s_red[k][w];
            s_inv[k] = (t > 0.f) ? (1.0f / t) : 0.f;
        }
    }
    if (tid < 16) {
        int t = s_warp[tid];
        int p = t;
#pragma unroll
        for (int o = 1; o < 16; o <<= 1) {
            int u = __shfl_up_sync(0xffffu, p, o);
            if (tid >= o) p += u;
        }
        s_warp[tid] = p - t;
        if (tid == 15) s_tot = p;
    }
    __syncthreads();

    int tot_packed = s_tot;
    int tot0 = tot_packed & 1023;
    int tot1 = (tot_packed >> 10) & 1023;
    int tot2 = (tot_packed >> 20) & 1023;
    int tot = tot0 + tot1 + tot2;
    int base_k[3];
    base_k[0] = 0;
    base_k[1] = tot0;
    base_k[2] = tot0 + tot1;

    int excl = s_warp[wid] + incl - packed;
    int offk[3];
    offk[0] = base_k[0] + (excl & 1023);
    offk[1] = base_k[1] + ((excl >> 10) & 1023);
    offk[2] = base_k[2] + ((excl >> 20) & 1023);

    // ---- phase 2: write packed (p/sum, k*NN+m) pair list
    if (tid < cnt) {
        unsigned m = s_list[tid] >> 6;
        float iv[3] = {s_inv[0], s_inv[1], s_inv[2]};
#pragma unroll
        for (int k = 0; k < 3; k++) {
            float p = s_p[k][tid];
            if (p != 0.f) {
                unsigned off32 = (unsigned)(k * NN) + m;
                s_pair[offk[k]] =
                    (unsigned long long)__float_as_uint(p * iv[k]) |
                    ((unsigned long long)off32 << 32);
                offk[k]++;
            }
        }
    }
    __syncthreads();

    // ---- phase 3: 16-warp row gather. One LDG.128 per warp = full 512B row.
    float a0 = 0.f, a1 = 0.f, a2 = 0.f, a3 = 0.f;
    float a4 = 0.f, a5 = 0.f, a6 = 0.f, a7 = 0.f;
#pragma unroll 4
    for (int i = wid; i < tot; i += 16) {
        unsigned long long pr = s_pair[i];
        float p = __uint_as_float((unsigned)pr);
        unsigned off32 = (unsigned)(pr >> 32);
        const uint4* row = (const uint4*)(g_wxh + ((size_t)off32 << 8));
        uint4 v = row[lane];
        float2 f0 = __half22float2(*(__half2*)&v.x);
        float2 f1 = __half22float2(*(__half2*)&v.y);
        float2 f2 = __half22float2(*(__half2*)&v.z);
        float2 f3 = __half22float2(*(__half2*)&v.w);
        a0 += p * f0.x; a1 += p * f0.y;
        a2 += p * f1.x; a3 += p * f1.y;
        a4 += p * f2.x; a5 += p * f2.y;
        a6 += p * f3.x; a7 += p * f3.y;
    }

    {
        float* dst = &s_acc[wid][lane * 8];
        *(float4*)dst = make_float4(a0, a1, a2, a3);
        *(float4*)(dst + 4) = make_float4(a4, a5, a6, a7);
    }
    __syncthreads();

    // ---- final: reduce 16 warp partials per channel, ELU, store
    if (tid < 256) {
        float t = s_acc[0][tid];
#pragma unroll
        for (int w = 1; w < 16; w++) t += s_acc[w][tid];
        float o = (t > 0.f) ? t : expm1f(t);
        out[(size_t)n * DOUT + tid] = o;
    }
}

// ---------------------------------------------------------------------------
extern "C" void kernel_launch(void* const* d_in, const int* in_sizes, int n_in,
                              void* d_out, int out_size) {
    const float* x        = (const float*)d_in[0];
    const int*   supports = (const int*)d_in[1];
    const int*   atten    = (const int*)d_in[2];
    const float* Wt       = (const float*)d_in[3];
    const float* Wl       = (const float*)d_in[4];
    const float* Wr       = (const float*)d_in[5];
    float* out = (float*)d_out;

    fused_gemm_alar<<<TOTAL_BLOCKS, 256>>>(x, Wt, Wl, Wr);
    attn_kernel<<<NN, ATHR>>>(supports, atten, out);
}

// round 16
// speedup vs baseline: 1.2464x; 1.2464x over previous
#include <cuda_runtime.h>
#include <cuda_fp16.h>
#include <math.h>

#define NN 4096
#define DIN 256
#define DOUT 256
#define KH 3
#define CAP 384
#define ALAR_BLOCKS 96
#define GEMM_BLOCKS 768
#define TOTAL_BLOCKS (ALAR_BLOCKS + GEMM_BLOCKS)
#define AP 20                 // smem half-row pitch (pad vs bank conflicts)
#define ATHR 512

// scratch (device globals: no allocation allowed)
__device__ __half g_wxh[KH * NN * DOUT];         // 6 MB fp16 (for gather)
__device__ float  g_al[KH * NN * 4];
__device__ float  g_ar[KH * NN * 4];

__device__ __forceinline__ void mma_16816(float c[4], unsigned a0, unsigned a1,
                                          unsigned a2, unsigned a3,
                                          unsigned b0, unsigned b1) {
    asm volatile(
        "mma.sync.aligned.m16n8k16.row.col.f32.f16.f16.f32 "
        "{%0,%1,%2,%3}, {%4,%5,%6,%7}, {%8,%9}, {%0,%1,%2,%3};"
        : "+f"(c[0]), "+f"(c[1]), "+f"(c[2]), "+f"(c[3])
        : "r"(a0), "r"(a1), "r"(a2), "r"(a3), "r"(b0), "r"(b1));
}

// pack 4 0/1 ints into 4 bytes of one u32
__device__ __forceinline__ unsigned pk01(int4 v) {
    return (unsigned)v.x | ((unsigned)v.y << 8) |
           ((unsigned)v.z << 16) | ((unsigned)v.w << 24);
}

// ---------------------------------------------------------------------------
// Kernel A: [al/ar via combined weights, parallel Wc] + [HMMA GEMM -> wxh]
// ---------------------------------------------------------------------------
__global__ void __launch_bounds__(256)
fused_gemm_alar(const float* __restrict__ x,
                const float* __restrict__ Wt,
                const float* __restrict__ Wl,
                const float* __restrict__ Wr) {
    __shared__ __align__(16) char smem_raw[16384];

    int bid = blockIdx.x;               // 0 .. 863
    int tx  = threadIdx.x;

    if (bid < ALAR_BLOCKS) {
        // ---------------- alar path: al/ar = x @ (Wt @ W{l,r}.T), fp32 -----
        float* sW  = (float*)smem_raw;          // [8][256] w-rows
        float* sWc = sW + 8 * 256;              // [256][8] combined weights
        int k = bid / 32;
        int chunk = bid % 32;

        // stage 0: load the 8 Wl/Wr rows into smem (warp j loads row j)
        {
            int j = tx >> 5;
            int lane = tx & 31;
            const float* wrow = (j < 4) ? (Wl + (size_t)(k * 4 + j) * DOUT)
                                        : (Wr + (size_t)(k * 4 + (j - 4)) * DOUT);
#pragma unroll
            for (int d = lane * 4; d < 256; d += 128) {
                float4 v = *(const float4*)(wrow + d);
                *(float4*)&sW[j * 256 + d] = v;
            }
        }
        __syncthreads();

        // stage 1 (parallel): thread c computes Wc[c][0..8)
        {
            int c = tx;
            const float* wtc = Wt + (size_t)k * DIN * DOUT + (size_t)c * DOUT;
            float acc[8];
#pragma unroll
            for (int j = 0; j < 8; j++) acc[j] = 0.f;
#pragma unroll 4
            for (int d4 = 0; d4 < 64; d4++) {
                float4 t = *(const float4*)(wtc + d4 * 4);
#pragma unroll
                for (int j = 0; j < 8; j++) {
                    float4 w = *(const float4*)&sW[j * 256 + d4 * 4];
                    acc[j] += t.x * w.x + t.y * w.y + t.z * w.z + t.w * w.w;
                }
            }
#pragma unroll
            for (int j = 0; j < 8; j++) sWc[c * 8 + j] = acc[j];
        }
        __syncthreads();

        // stage 2: al/ar rows for this chunk
        int rl = tx >> 3;
        int j = tx & 7;
#pragma unroll
        for (int it = 0; it < 4; it++) {
            int row = chunk * 128 + it * 32 + rl;
            const float* xr = x + (size_t)row * DIN;
            float acc = 0.f;
#pragma unroll 8
            for (int c4 = 0; c4 < 64; c4++) {
                float4 xv = *(const float4*)(xr + c4 * 4);
                acc += xv.x * sWc[(c4 * 4 + 0) * 8 + j] +
                       xv.y * sWc[(c4 * 4 + 1) * 8 + j] +
                       xv.z * sWc[(c4 * 4 + 2) * 8 + j] +
                       xv.w * sWc[(c4 * 4 + 3) * 8 + j];
            }
            if (j < 4)
                g_al[((size_t)k * NN + row) * 4 + j] = acc;
            else
                g_ar[((size_t)k * NN + row) * 4 + (j - 4)] = acc;
        }
        return;
    }

    // ---------------- GEMM path (single fp16 HMMA) -------------------------
    {
        __half* sA  = (__half*)smem_raw;                  // 64*AP
        __half* sBt = sA + 64 * AP;

        int gid = bid - ALAR_BLOCKS;    // 0..767
        int k = gid >> 8;
        int rem = gid & 255;
        int row0 = (rem >> 2) * 64;
        int col0 = (rem & 3) * 64;
        const float* B = Wt + (size_t)k * DIN * DOUT;

        int wid = tx >> 5;
        int lane = tx & 31;
        int g = lane >> 2;
        int tg = lane & 3;
        int moff = (wid >> 1) * 16;
        int noff = (wid & 1) * 32;

        float c[4][4];
#pragma unroll
        for (int i = 0; i < 4; i++)
#pragma unroll
            for (int j = 0; j < 4; j++) c[i][j] = 0.f;

        int lm = tx >> 2;
        int lk4 = (tx & 3) * 4;
        int lkr = tx >> 4;
        int ln4 = (tx & 15) * 4;

        for (int ks = 0; ks < 16; ks++) {
            int kk = ks * 16;
            {
                float4 v = *(const float4*)(x + (size_t)(row0 + lm) * DIN + kk + lk4);
                *(__half2*)&sA[lm * AP + lk4]     = __floats2half2_rn(v.x, v.y);
                *(__half2*)&sA[lm * AP + lk4 + 2] = __floats2half2_rn(v.z, v.w);
            }
            {
                float4 w = *(const float4*)(B + (size_t)(kk + lkr) * DOUT + col0 + ln4);
                sBt[(ln4 + 0) * AP + lkr] = __float2half_rn(w.x);
                sBt[(ln4 + 1) * AP + lkr] = __float2half_rn(w.y);
                sBt[(ln4 + 2) * AP + lkr] = __float2half_rn(w.z);
                sBt[(ln4 + 3) * AP + lkr] = __float2half_rn(w.w);
            }
            __syncthreads();

            unsigned a0 = *(unsigned*)&sA[(moff + g) * AP + tg * 2];
            unsigned a1 = *(unsigned*)&sA[(moff + g + 8) * AP + tg * 2];
            unsigned a2 = *(unsigned*)&sA[(moff + g) * AP + tg * 2 + 8];
            unsigned a3 = *(unsigned*)&sA[(moff + g + 8) * AP + tg * 2 + 8];
#pragma unroll
            for (int nb = 0; nb < 4; nb++) {
                unsigned b0 = *(unsigned*)&sBt[(noff + nb * 8 + g) * AP + tg * 2];
                unsigned b1 = *(unsigned*)&sBt[(noff + nb * 8 + g) * AP + tg * 2 + 8];
                mma_16816(c[nb], a0, a1, a2, a3, b0, b1);
            }
            __syncthreads();
        }

        size_t kplane = (size_t)k * NN * DOUT;
#pragma unroll
        for (int nb = 0; nb < 4; nb++) {
            int gcol = col0 + noff + nb * 8 + tg * 2;
            size_t o0 = kplane + (size_t)(row0 + moff + g) * DOUT + gcol;
            size_t o1 = kplane + (size_t)(row0 + moff + g + 8) * DOUT + gcol;
            *(__half2*)(g_wxh + o0) = __floats2half2_rn(c[nb][0], c[nb][1]);
            *(__half2*)(g_wxh + o1) = __floats2half2_rn(c[nb][2], c[nb][3]);
        }
    }
}

// ---------------------------------------------------------------------------
// Kernel C: per-row attention, 512 threads, 4 blocks/SM. Reads the 6 mask
// rows directly; compact -> score+exp+sum -> pair write -> 16-warp gather.
// ---------------------------------------------------------------------------
__global__ void __launch_bounds__(ATHR, 4)
attn_kernel(const int* __restrict__ supports,
            const int* __restrict__ atten,
            float* __restrict__ out) {
    int n = blockIdx.x;
    int tid = threadIdx.x;
    int lane = tid & 31;
    int wid = tid >> 5;                 // 0..15

    __shared__ unsigned s_list[CAP];
    __shared__ float s_p[3][CAP];
    __shared__ unsigned long long s_pair[3 * CAP];
    __shared__ float s_acc[16][256];
    __shared__ float s_al[3][4];
    __shared__ float s_red[3][16];
    __shared__ float s_inv[3];
    __shared__ int s_warp[16];
    __shared__ int s_tot;
    __shared__ int s_cnt;

    if (tid < 12) {
        int k = tid >> 2, j = tid & 3;
        s_al[k][j] = g_al[((size_t)k * NN + n) * 4 + j];
    }

    // ---- phase 0: read 6 mask rows directly; pack codes for my 8 positions
    const int4* pa0 = (const int4*)(atten + ((size_t)0 * NN + n) * NN);
    const int4* pa1 = (const int4*)(atten + ((size_t)1 * NN + n) * NN);
    const int4* pa2 = (const int4*)(atten + ((size_t)2 * NN + n) * NN);
    const int4* ps0 = (const int4*)(supports + ((size_t)0 * NN + n) * NN);
    const int4* ps1 = (const int4*)(supports + ((size_t)1 * NN + n) * NN);
    const int4* ps2 = (const int4*)(supports + ((size_t)2 * NN + n) * NN);

    int i0 = tid * 2;                   // int4 index; my elems = tid*8..+7
    int4 A0 = __ldcs(pa0 + i0), B0 = __ldcs(pa0 + i0 + 1);
    int4 A1 = __ldcs(pa1 + i0), B1 = __ldcs(pa1 + i0 + 1);
    int4 A2 = __ldcs(pa2 + i0), B2 = __ldcs(pa2 + i0 + 1);
    int4 Q0 = __ldcs(ps0 + i0), T0 = __ldcs(ps0 + i0 + 1);
    int4 Q1 = __ldcs(ps1 + i0), T1 = __ldcs(ps1 + i0 + 1);
    int4 Q2 = __ldcs(ps2 + i0), T2 = __ldcs(ps2 + i0 + 1);

    unsigned w2[2];
    w2[0] = pk01(A0) | (pk01(A1) << 1) | (pk01(A2) << 2) |
            (pk01(Q0) << 3) | (pk01(Q1) << 4) | (pk01(Q2) << 5);
    w2[1] = pk01(B0) | (pk01(B1) << 1) | (pk01(B2) << 2) |
            (pk01(T0) << 3) | (pk01(T1) << 4) | (pk01(T2) << 5);

    int cnt_local = 0;
#pragma unroll
    for (int q = 0; q < 2; q++)
        cnt_local += __popc(__vcmpne4(w2[q], 0u)) >> 3;

    {
        int incl = cnt_local;
#pragma unroll
        for (int o = 1; o < 32; o <<= 1) {
            int t = __shfl_up_sync(0xffffffffu, incl, o);
            if (lane >= o) incl += t;
        }
        if (lane == 31) s_warp[wid] = incl;
        __syncthreads();
        if (tid < 16) {
            int t = s_warp[tid];
            int p = t;
#pragma unroll
            for (int o = 1; o < 16; o <<= 1) {
                int u = __shfl_up_sync(0xffffu, p, o);
                if (tid >= o) p += u;
            }
            s_warp[tid] = p - t;
            if (tid == 15) s_cnt = p;
        }
        __syncthreads();
        int off = s_warp[wid] + incl - cnt_local;
#pragma unroll
        for (int q = 0; q < 2; q++) {
#pragma unroll
            for (int j = 0; j < 4; j++) {
                unsigned c = (w2[q] >> (8 * j)) & 255u;
                if (c) {
                    unsigned m = (unsigned)(tid * 8 + q * 4 + j);
                    if (off < CAP) s_list[off] = (m << 6) | c;
                    off++;
                }
            }
        }
    }
    __syncthreads();
    int cnt = min(s_cnt, CAP);

    // ---- phase 1: scores + exp + sum + counts, single shot (cnt < 512)
    float sm[3] = {0.f, 0.f, 0.f};
    int ck[3] = {0, 0, 0};
    if (tid < cnt) {
        unsigned v = s_list[tid];
        int m = (int)(v >> 6);
        int code = (int)(v & 63u);
#pragma unroll
        for (int k = 0; k < 3; k++) {
            float4 arv = *(const float4*)(g_ar + ((size_t)k * NN + m) * 4);
            float s = 0.f;
            if (code & 1) s += s_al[k][0] + arv.x;
            if (code & 2) s += s_al[k][1] + arv.y;
            if (code & 4) s += s_al[k][2] + arv.z;
            if (code & (8 << k)) s += s_al[k][3] + arv.w;
            float p = (s != 0.f) ? __expf(s) : 0.f;
            s_p[k][tid] = p;
            sm[k] = p;
            ck[k] = (p != 0.f);
        }
    }
#pragma unroll
    for (int k = 0; k < 3; k++)
#pragma unroll
        for (int o = 16; o; o >>= 1)
            sm[k] += __shfl_xor_sync(0xffffffffu, sm[k], o);
    if (lane == 0) {
#pragma unroll
        for (int k = 0; k < 3; k++) s_red[k][wid] = sm[k];
    }

    int packed = ck[0] | (ck[1] << 10) | (ck[2] << 20);
    int incl = packed;
#pragma unroll
    for (int o = 1; o < 32; o <<= 1) {
        int t = __shfl_up_sync(0xffffffffu, incl, o);
        if (lane >= o) incl += t;
    }
    if (lane == 31) s_warp[wid] = incl;
    __syncthreads();
    if (tid == 0) {
#pragma unroll
        for (int k = 0; k < 3; k++) {
            float t = 0.f;
#pragma unroll
            for (int w = 0; w < 16; w++) t += s_red[k][w];
            s_inv[k] = (t > 0.f) ? (1.0f / t) : 0.f;
        }
    }
    if (tid < 16) {
        int t = s_warp[tid];
        int p = t;
#pragma unroll
        for (int o = 1; o < 16; o <<= 1) {
            int u = __shfl_up_sync(0xffffu, p, o);
            if (tid >= o) p += u;
        }
        s_warp[tid] = p - t;
        if (tid == 15) s_tot = p;
    }
    __syncthreads();

    int tot_packed = s_tot;
    int tot0 = tot_packed & 1023;
    int tot1 = (tot_packed >> 10) & 1023;
    int tot2 = (tot_packed >> 20) & 1023;
    int tot = tot0 + tot1 + tot2;
    int base_k[3];
    base_k[0] = 0;
    base_k[1] = tot0;
    base_k[2] = tot0 + tot1;

    int excl = s_warp[wid] + incl - packed;
    int offk[3];
    offk[0] = base_k[0] + (excl & 1023);
    offk[1] = base_k[1] + ((excl >> 10) & 1023);
    offk[2] = base_k[2] + ((excl >> 20) & 1023);

    // ---- phase 2: write packed (p/sum, k*NN+m) pair list
    if (tid < cnt) {
        unsigned m = s_list[tid] >> 6;
        float iv[3] = {s_inv[0], s_inv[1], s_inv[2]};
#pragma unroll
        for (int k = 0; k < 3; k++) {
            float p = s_p[k][tid];
            if (p != 0.f) {
                unsigned off32 = (unsigned)(k * NN) + m;
                s_pair[offk[k]] =
                    (unsigned long long)__float_as_uint(p * iv[k]) |
                    ((unsigned long long)off32 << 32);
                offk[k]++;
            }
        }
    }
    __syncthreads();

    // ---- phase 3: 16-warp row gather. One LDG.128 per warp = full 512B row.
    float a0 = 0.f, a1 = 0.f, a2 = 0.f, a3 = 0.f;
    float a4 = 0.f, a5 = 0.f, a6 = 0.f, a7 = 0.f;
#pragma unroll 4
    for (int i = wid; i < tot; i += 16) {
        unsigned long long pr = s_pair[i];
        float p = __uint_as_float((unsigned)pr);
        unsigned off32 = (unsigned)(pr >> 32);
        const uint4* row = (const uint4*)(g_wxh + ((size_t)off32 << 8));
        uint4 v = row[lane];
        float2 f0 = __half22float2(*(__half2*)&v.x);
        float2 f1 = __half22float2(*(__half2*)&v.y);
        float2 f2 = __half22float2(*(__half2*)&v.z);
        float2 f3 = __half22float2(*(__half2*)&v.w);
        a0 += p * f0.x; a1 += p * f0.y;
        a2 += p * f1.x; a3 += p * f1.y;
        a4 += p * f2.x; a5 += p * f2.y;
        a6 += p * f3.x; a7 += p * f3.y;
    }

    {
        float* dst = &s_acc[wid][lane * 8];
        *(float4*)dst = make_float4(a0, a1, a2, a3);
        *(float4*)(dst + 4) = make_float4(a4, a5, a6, a7);
    }
    __syncthreads();

    // ---- final: reduce 16 warp partials per channel, ELU, store
    if (tid < 256) {
        float t = s_acc[0][tid];
#pragma unroll
        for (int w = 1; w < 16; w++) t += s_acc[w][tid];
        float o = (t > 0.f) ? t : expm1f(t);
        out[(size_t)n * DOUT + tid] = o;
    }
}

// ---------------------------------------------------------------------------
extern "C" void kernel_launch(void* const* d_in, const int* in_sizes, int n_in,
                              void* d_out, int out_size) {
    const float* x        = (const float*)d_in[0];
    const int*   supports = (const int*)d_in[1];
    const int*   atten    = (const int*)d_in[2];
    const float* Wt       = (const float*)d_in[3];
    const float* Wl       = (const float*)d_in[4];
    const float* Wr       = (const float*)d_in[5];
    float* out = (float*)d_out;

    fused_gemm_alar<<<TOTAL_BLOCKS, 256>>>(x, Wt, Wl, Wr);
    attn_kernel<<<NN, ATHR>>>(supports, atten, out);
}